// round 3
// baseline (speedup 1.0000x reference)
#include <cuda_runtime.h>
#include <math.h>

#define N_NODES 50000
#define N_EDGES 800000
#define D_IN    64
#define D_HID   256
#define BN_EPS  1e-5f
#define NB      8   // nodes per block in GEMM kernels

// ---------------- scratch (no allocs allowed) ----------------
__device__ float g_dinv[N_NODES];                                  // degree -> rsqrt(degree)
__device__ __align__(16) float g_h[(size_t)N_NODES * D_HID];       // h' = (xs@W_gcn) * dinv[row]
__device__ __align__(16) float g_z[(size_t)N_NODES * D_HID];       // scatter accumulator -> tanh(z)
__device__ float g_sum[D_HID];
__device__ float g_sumsq[D_HID];

// ---------------- K0: init degree=1 (self loop), zero BN stats ----------------
__global__ void k_init() {
    int i = blockIdx.x * blockDim.x + threadIdx.x;
    if (i < N_NODES) g_dinv[i] = 1.0f;
    if (i < D_HID) { g_sum[i] = 0.0f; g_sumsq[i] = 0.0f; }
}

// ---------------- K1: degree histogram over dst (edge_index is int32) ----------------
__global__ void k_degree(const int* __restrict__ ei) {
    int e = blockIdx.x * blockDim.x + threadIdx.x;
    if (e < N_EDGES) {
        int d = ei[N_EDGES + e];
        atomicAdd(&g_dinv[d], 1.0f);
    }
}

// ---------------- K2: dinv = rsqrt(deg) ----------------
__global__ void k_rsqrt() {
    int i = blockIdx.x * blockDim.x + threadIdx.x;
    if (i < N_NODES) g_dinv[i] = rsqrtf(g_dinv[i]);
}

// ---------------- K3: h' = (xs @ W_gcn) * dinv[row]; z init = self-loop term ----------------
__global__ void __launch_bounds__(D_HID) k_gcn_gemm(const float* __restrict__ xs,
                                                    const float* __restrict__ Wg) {
    __shared__ float sx[NB * D_IN];           // 8 rows of xs
    int n0 = blockIdx.x * NB;
    int j  = threadIdx.x;                     // output column 0..255

    // 8*64 = 512 contiguous floats
    sx[j]       = xs[(size_t)n0 * D_IN + j];
    sx[j + 256] = xs[(size_t)n0 * D_IN + 256 + j];
    __syncthreads();

    float acc[NB];
#pragma unroll
    for (int nb = 0; nb < NB; nb++) acc[nb] = 0.0f;

#pragma unroll 8
    for (int k = 0; k < D_IN; k++) {
        float w = Wg[k * D_HID + j];
#pragma unroll
        for (int nb = 0; nb < NB; nb++) acc[nb] += sx[nb * D_IN + k] * w;
    }

#pragma unroll
    for (int nb = 0; nb < NB; nb++) {
        float v = acc[nb] * g_dinv[n0 + nb];
        size_t o = (size_t)(n0 + nb) * D_HID + j;
        g_h[o] = v;     // message value
        g_z[o] = v;     // self-loop contribution initializes accumulator
    }
}

// ---------------- K4: edge scatter, one warp per edge, red.v4 ----------------
__global__ void __launch_bounds__(256) k_scatter(const int* __restrict__ ei) {
    int e    = (int)((blockIdx.x * (size_t)blockDim.x + threadIdx.x) >> 5);
    int lane = threadIdx.x & 31;
    if (e >= N_EDGES) return;
    int s = ei[e];
    int d = ei[N_EDGES + e];
    const float4* hp = (const float4*)(g_h + (size_t)s * D_HID);
    float4*       zp = (float4*)(g_z + (size_t)d * D_HID);
#pragma unroll
    for (int i = 0; i < 2; i++) {
        float4 v = hp[lane + 32 * i];
        float4* p = zp + lane + 32 * i;
        asm volatile("red.global.add.v4.f32 [%0], {%1,%2,%3,%4};"
                     :: "l"(p), "f"(v.x), "f"(v.y), "f"(v.z), "f"(v.w)
                     : "memory");
    }
}

// ---------------- K5: z = tanh(dinv[row]*acc + b_gcn) ----------------
__global__ void k_ztanh(const float* __restrict__ b_gcn) {
    size_t i = (size_t)blockIdx.x * blockDim.x + threadIdx.x;
    if (i < (size_t)N_NODES * D_HID) {
        int row = (int)(i >> 8);
        int col = (int)(i & 255);
        g_z[i] = tanhf(g_dinv[row] * g_z[i] + b_gcn[col]);
    }
}

// ---------------- K6: fused gate GEMM + lin GEMM + residual + relu ----------------
__global__ void __launch_bounds__(D_HID) k_gate(const float* __restrict__ xs,
                                                const float* __restrict__ Wgate,
                                                const float* __restrict__ b_gate,
                                                const float* __restrict__ Wlin,
                                                const float* __restrict__ b_lin,
                                                float* __restrict__ out) {
    __shared__ float sz[NB * D_HID];   // 8 z rows (8 KB)
    __shared__ float sx[NB * D_IN];    // 8 xs rows (2 KB)
    int n0 = blockIdx.x * NB;
    int j  = threadIdx.x;

#pragma unroll
    for (int t = 0; t < NB; t++)
        sz[j + 256 * t] = g_z[(size_t)n0 * D_HID + j + 256 * t];
    sx[j]       = xs[(size_t)n0 * D_IN + j];
    sx[j + 256] = xs[(size_t)n0 * D_IN + 256 + j];
    __syncthreads();

    float bg = b_gate[j], bl = b_lin[j];
    float accg[NB], accl[NB];
#pragma unroll
    for (int nb = 0; nb < NB; nb++) { accg[nb] = bg; accl[nb] = bl; }

    // gate GEMM: K = 256, vectorized smem reads (broadcast, conflict-free)
#pragma unroll 4
    for (int k4 = 0; k4 < D_HID / 4; k4++) {
        float w0 = Wgate[(4 * k4 + 0) * D_HID + j];
        float w1 = Wgate[(4 * k4 + 1) * D_HID + j];
        float w2 = Wgate[(4 * k4 + 2) * D_HID + j];
        float w3 = Wgate[(4 * k4 + 3) * D_HID + j];
#pragma unroll
        for (int nb = 0; nb < NB; nb++) {
            float4 zv = ((const float4*)(sz + nb * D_HID))[k4];
            accg[nb] += zv.x * w0;
            accg[nb] += zv.y * w1;
            accg[nb] += zv.z * w2;
            accg[nb] += zv.w * w3;
        }
    }

    // lin GEMM: K = 64
#pragma unroll 4
    for (int k4 = 0; k4 < D_IN / 4; k4++) {
        float w0 = Wlin[(4 * k4 + 0) * D_HID + j];
        float w1 = Wlin[(4 * k4 + 1) * D_HID + j];
        float w2 = Wlin[(4 * k4 + 2) * D_HID + j];
        float w3 = Wlin[(4 * k4 + 3) * D_HID + j];
#pragma unroll
        for (int nb = 0; nb < NB; nb++) {
            float4 xv = ((const float4*)(sx + nb * D_IN))[k4];
            accl[nb] += xv.x * w0;
            accl[nb] += xv.y * w1;
            accl[nb] += xv.z * w2;
            accl[nb] += xv.w * w3;
        }
    }

#pragma unroll
    for (int nb = 0; nb < NB; nb++) {
        float g = 1.0f / (1.0f + expf(-accg[nb]));
        float z = sz[nb * D_HID + j];
        float o = (1.0f - g) * accl[nb] + g * z;
        out[(size_t)(n0 + nb) * D_HID + j] = fmaxf(o, 0.0f);
    }
}

// ---------------- K7: BN partial stats (per-column sum / sumsq) ----------------
__global__ void __launch_bounds__(D_HID) k_stats(const float* __restrict__ out) {
    int j = threadIdx.x;
    int rows_per_block = (N_NODES + gridDim.x - 1) / gridDim.x;
    int r0 = blockIdx.x * rows_per_block;
    int r1 = r0 + rows_per_block;
    if (r1 > N_NODES) r1 = N_NODES;
    float s = 0.0f, q = 0.0f;
    for (int r = r0; r < r1; r++) {
        float v = out[(size_t)r * D_HID + j];
        s += v;
        q += v * v;
    }
    if (r1 > r0) {
        atomicAdd(&g_sum[j], s);
        atomicAdd(&g_sumsq[j], q);
    }
}

// ---------------- K8: BN normalize in place ----------------
__global__ void k_bn(float* __restrict__ out,
                     const float* __restrict__ gamma,
                     const float* __restrict__ beta) {
    size_t i = (size_t)blockIdx.x * blockDim.x + threadIdx.x;
    if (i < (size_t)N_NODES * D_HID) {
        int col = (int)(i & 255);
        const float invN = 1.0f / (float)N_NODES;
        float mu  = g_sum[col] * invN;
        float var = g_sumsq[col] * invN - mu * mu;
        out[i] = (out[i] - mu) * rsqrtf(var + BN_EPS) * gamma[col] + beta[col];
    }
}

// ---------------- launch ----------------
extern "C" void kernel_launch(void* const* d_in, const int* in_sizes, int n_in,
                              void* d_out, int out_size) {
    const float* xs     = (const float*)d_in[0];
    const int*   ei     = (const int*)d_in[1];     // int32: JAX x64-disabled downcasts int64
    const float* W_gcn  = (const float*)d_in[2];
    const float* b_gcn  = (const float*)d_in[3];
    const float* W_lin  = (const float*)d_in[4];
    const float* b_lin  = (const float*)d_in[5];
    const float* W_gate = (const float*)d_in[6];
    const float* b_gate = (const float*)d_in[7];
    const float* gamma  = (const float*)d_in[8];
    const float* beta   = (const float*)d_in[9];
    float* out = (float*)d_out;

    k_init<<<(N_NODES + 255) / 256, 256>>>();
    k_degree<<<(N_EDGES + 255) / 256, 256>>>(ei);
    k_rsqrt<<<(N_NODES + 255) / 256, 256>>>();
    k_gcn_gemm<<<N_NODES / NB, D_HID>>>(xs, W_gcn);
    k_scatter<<<(N_EDGES * 32) / 256, 256>>>(ei);
    k_ztanh<<<(N_NODES * D_HID + 255) / 256, 256>>>(b_gcn);
    k_gate<<<N_NODES / NB, D_HID>>>(xs, W_gate, b_gate, W_lin, b_lin, out);
    k_stats<<<512, D_HID>>>(out);
    k_bn<<<(N_NODES * D_HID + 255) / 256, 256>>>(out, gamma, beta);
}

// round 8
// speedup vs baseline: 1.2463x; 1.2463x over previous
#include <cuda_runtime.h>
#include <math.h>

#define N_NODES 50000
#define N_EDGES 800000
#define D_IN    64
#define D_HID   256
#define BN_EPS  1e-5f
#define NB      8   // nodes per block in GEMM kernels

// ---------------- scratch (no allocs allowed) ----------------
__device__ float g_dinv[N_NODES];
__device__ __align__(16) float g_h[(size_t)N_NODES * D_HID];   // h' = (xs@W_gcn) * dinv[row]
__device__ __align__(16) float g_z[(size_t)N_NODES * D_HID];   // tanh(norm-aggregated)
__device__ float g_sum[D_HID];
__device__ float g_sumsq[D_HID];
// CSR scratch
__device__ int g_deg[N_NODES];
__device__ int g_rowptr[N_NODES + 1];
__device__ int g_cursor[N_NODES];
__device__ int g_csrc[N_EDGES];

// ---------------- packed f32x2 helpers (FFMA2 on sm_103a) ----------------
__device__ __forceinline__ unsigned long long pk2(float lo, float hi) {
    unsigned long long r;
    asm("mov.b64 %0, {%1, %2};" : "=l"(r) : "f"(lo), "f"(hi));
    return r;
}
__device__ __forceinline__ float2 upk2(unsigned long long v) {
    float2 f;
    asm("mov.b64 {%0, %1}, %2;" : "=f"(f.x), "=f"(f.y) : "l"(v));
    return f;
}
__device__ __forceinline__ void fma2(unsigned long long& d, unsigned long long a,
                                     unsigned long long b) {
    asm("fma.rn.f32x2 %0, %1, %2, %0;" : "+l"(d) : "l"(a), "l"(b));
}

// ---------------- K0: zero degree + BN stats ----------------
__global__ void k_init() {
    int i = blockIdx.x * blockDim.x + threadIdx.x;
    if (i < N_NODES) g_deg[i] = 0;
    if (i < D_HID) { g_sum[i] = 0.0f; g_sumsq[i] = 0.0f; }
}

// ---------------- K1: degree histogram over dst ----------------
__global__ void k_degree(const int* __restrict__ ei) {
    int e = blockIdx.x * blockDim.x + threadIdx.x;
    if (e < N_EDGES) atomicAdd(&g_deg[ei[N_EDGES + e]], 1);
}

// ---------------- K2: single-block prefix scan -> rowptr/cursor, dinv ----------------
__global__ void __launch_bounds__(1024) k_scan() {
    __shared__ int warpsums[32];
    int t = threadIdx.x, lane = t & 31, w = t >> 5;
    int carry = 0;
    for (int base = 0; base < N_NODES; base += 1024) {
        int i = base + t;
        int v = (i < N_NODES) ? g_deg[i] : 0;
        int x = v;
#pragma unroll
        for (int off = 1; off < 32; off <<= 1) {
            int y = __shfl_up_sync(0xffffffffu, x, off);
            if (lane >= off) x += y;
        }
        if (lane == 31) warpsums[w] = x;
        __syncthreads();
        if (w == 0) {
            int s = warpsums[lane];
#pragma unroll
            for (int off = 1; off < 32; off <<= 1) {
                int y = __shfl_up_sync(0xffffffffu, s, off);
                if (lane >= off) s += y;
            }
            warpsums[lane] = s;
        }
        __syncthreads();
        int woff = (w > 0) ? warpsums[w - 1] : 0;
        int excl = carry + woff + x - v;
        if (i < N_NODES) {
            g_rowptr[i] = excl;
            g_cursor[i] = excl;
            g_dinv[i] = rsqrtf((float)(v + 1));   // +1 self loop
        }
        int tile_total = warpsums[31];
        __syncthreads();   // protect warpsums before next tile overwrites
        carry += tile_total;
    }
    if (t == 0) g_rowptr[N_NODES] = carry;
}

// ---------------- K3: CSR fill ----------------
__global__ void k_fill(const int* __restrict__ ei) {
    int e = blockIdx.x * blockDim.x + threadIdx.x;
    if (e < N_EDGES) {
        int s = ei[e];
        int d = ei[N_EDGES + e];
        int pos = atomicAdd(&g_cursor[d], 1);
        g_csrc[pos] = s;
    }
}

// ---------------- K4: h' = (xs @ W_gcn) * dinv[row]  (FFMA2) ----------------
__global__ void __launch_bounds__(D_HID) k_gcn_gemm(const float* __restrict__ xs,
                                                    const float* __restrict__ Wg) {
    __shared__ __align__(16) float sx[NB * D_IN];
    int n0 = blockIdx.x * NB;
    int j  = threadIdx.x;

    sx[j]       = xs[(size_t)n0 * D_IN + j];
    sx[j + 256] = xs[(size_t)n0 * D_IN + 256 + j];
    __syncthreads();

    unsigned long long acc2[NB];
#pragma unroll
    for (int nb = 0; nb < NB; nb++) acc2[nb] = 0ULL;

#pragma unroll 4
    for (int k4 = 0; k4 < D_IN / 4; k4++) {
        float w0 = Wg[(4 * k4 + 0) * D_HID + j];
        float w1 = Wg[(4 * k4 + 1) * D_HID + j];
        float w2 = Wg[(4 * k4 + 2) * D_HID + j];
        float w3 = Wg[(4 * k4 + 3) * D_HID + j];
        unsigned long long wp0 = pk2(w0, w1), wp1 = pk2(w2, w3);
#pragma unroll
        for (int nb = 0; nb < NB; nb++) {
            ulonglong2 zz = ((const ulonglong2*)(sx + nb * D_IN))[k4];
            fma2(acc2[nb], zz.x, wp0);
            fma2(acc2[nb], zz.y, wp1);
        }
    }

#pragma unroll
    for (int nb = 0; nb < NB; nb++) {
        float2 f = upk2(acc2[nb]);
        g_h[(size_t)(n0 + nb) * D_HID + j] = (f.x + f.y) * g_dinv[n0 + nb];
    }
}

// ---------------- K5: CSR gather + self loop + tanh -> g_z ----------------
__global__ void __launch_bounds__(256) k_gather(const float* __restrict__ b_gcn) {
    int t = threadIdx.x;
    int n = blockIdx.x * 4 + (t >> 6);   // 4 nodes/block, 64 threads each
    int c = t & 63;                      // float4 column index
    const float4* H = (const float4*)g_h;

    float4 acc = H[(size_t)n * 64 + c];  // self-loop term (h' already carries dinv[n])
    int r = g_rowptr[n], e = g_rowptr[n + 1];
    for (; r + 4 <= e; r += 4) {
        int i0 = g_csrc[r], i1 = g_csrc[r + 1], i2 = g_csrc[r + 2], i3 = g_csrc[r + 3];
        float4 a0 = H[(size_t)i0 * 64 + c];
        float4 a1 = H[(size_t)i1 * 64 + c];
        float4 a2 = H[(size_t)i2 * 64 + c];
        float4 a3 = H[(size_t)i3 * 64 + c];
        acc.x += (a0.x + a1.x) + (a2.x + a3.x);
        acc.y += (a0.y + a1.y) + (a2.y + a3.y);
        acc.z += (a0.z + a1.z) + (a2.z + a3.z);
        acc.w += (a0.w + a1.w) + (a2.w + a3.w);
    }
    for (; r < e; r++) {
        int i0 = g_csrc[r];
        float4 a0 = H[(size_t)i0 * 64 + c];
        acc.x += a0.x; acc.y += a0.y; acc.z += a0.z; acc.w += a0.w;
    }
    float di = g_dinv[n];
    float4 b = ((const float4*)b_gcn)[c];
    float4 zt;
    zt.x = tanhf(acc.x * di + b.x);
    zt.y = tanhf(acc.y * di + b.y);
    zt.z = tanhf(acc.z * di + b.z);
    zt.w = tanhf(acc.w * di + b.w);
    ((float4*)g_z)[(size_t)n * 64 + c] = zt;
}

// ---------------- K6: gate GEMM + lin GEMM + residual + relu + BN stats (FFMA2) ----------------
__global__ void __launch_bounds__(D_HID) k_gate(const float* __restrict__ xs,
                                                const float* __restrict__ Wgate,
                                                const float* __restrict__ b_gate,
                                                const float* __restrict__ Wlin,
                                                const float* __restrict__ b_lin,
                                                float* __restrict__ out) {
    __shared__ __align__(16) float sz[NB * D_HID];   // 8 z rows (8 KB)
    __shared__ __align__(16) float sx[NB * D_IN];    // 8 xs rows (2 KB)
    int n0 = blockIdx.x * NB;
    int j  = threadIdx.x;

#pragma unroll
    for (int t = 0; t < NB; t++)
        sz[j + 256 * t] = g_z[(size_t)n0 * D_HID + j + 256 * t];
    sx[j]       = xs[(size_t)n0 * D_IN + j];
    sx[j + 256] = xs[(size_t)n0 * D_IN + 256 + j];
    __syncthreads();

    unsigned long long accg2[NB], accl2[NB];
#pragma unroll
    for (int nb = 0; nb < NB; nb++) { accg2[nb] = 0ULL; accl2[nb] = 0ULL; }

    // gate GEMM: K = 256, packed over k
#pragma unroll 4
    for (int k4 = 0; k4 < D_HID / 4; k4++) {
        float w0 = Wgate[(4 * k4 + 0) * D_HID + j];
        float w1 = Wgate[(4 * k4 + 1) * D_HID + j];
        float w2 = Wgate[(4 * k4 + 2) * D_HID + j];
        float w3 = Wgate[(4 * k4 + 3) * D_HID + j];
        unsigned long long wp0 = pk2(w0, w1), wp1 = pk2(w2, w3);
#pragma unroll
        for (int nb = 0; nb < NB; nb++) {
            ulonglong2 zz = ((const ulonglong2*)(sz + nb * D_HID))[k4];
            fma2(accg2[nb], zz.x, wp0);
            fma2(accg2[nb], zz.y, wp1);
        }
    }

    // lin GEMM: K = 64, packed over k
#pragma unroll 4
    for (int k4 = 0; k4 < D_IN / 4; k4++) {
        float w0 = Wlin[(4 * k4 + 0) * D_HID + j];
        float w1 = Wlin[(4 * k4 + 1) * D_HID + j];
        float w2 = Wlin[(4 * k4 + 2) * D_HID + j];
        float w3 = Wlin[(4 * k4 + 3) * D_HID + j];
        unsigned long long wp0 = pk2(w0, w1), wp1 = pk2(w2, w3);
#pragma unroll
        for (int nb = 0; nb < NB; nb++) {
            ulonglong2 xx = ((const ulonglong2*)(sx + nb * D_IN))[k4];
            fma2(accl2[nb], xx.x, wp0);
            fma2(accl2[nb], xx.y, wp1);
        }
    }

    float bg = b_gate[j], bl = b_lin[j];
    float s_loc = 0.0f, q_loc = 0.0f;
#pragma unroll
    for (int nb = 0; nb < NB; nb++) {
        float2 fg = upk2(accg2[nb]);
        float2 fl = upk2(accl2[nb]);
        float ag = fg.x + fg.y + bg;
        float al = fl.x + fl.y + bl;
        float g  = 1.0f / (1.0f + expf(-ag));
        float z  = sz[nb * D_HID + j];
        float o  = fmaxf((1.0f - g) * al + g * z, 0.0f);
        out[(size_t)(n0 + nb) * D_HID + j] = o;
        s_loc += o;
        q_loc += o * o;
    }
    atomicAdd(&g_sum[j], s_loc);
    atomicAdd(&g_sumsq[j], q_loc);
}

// ---------------- K7: BN normalize in place ----------------
__global__ void k_bn(float* __restrict__ out,
                     const float* __restrict__ gamma,
                     const float* __restrict__ beta) {
    size_t i = (size_t)blockIdx.x * blockDim.x + threadIdx.x;
    if (i < (size_t)N_NODES * D_HID) {
        int col = (int)(i & 255);
        const float invN = 1.0f / (float)N_NODES;
        float mu  = g_sum[col] * invN;
        float var = g_sumsq[col] * invN - mu * mu;
        out[i] = (out[i] - mu) * rsqrtf(var + BN_EPS) * gamma[col] + beta[col];
    }
}

// ---------------- launch ----------------
extern "C" void kernel_launch(void* const* d_in, const int* in_sizes, int n_in,
                              void* d_out, int out_size) {
    const float* xs     = (const float*)d_in[0];
    const int*   ei     = (const int*)d_in[1];   // int32 (JAX x64-disabled)
    const float* W_gcn  = (const float*)d_in[2];
    const float* b_gcn  = (const float*)d_in[3];
    const float* W_lin  = (const float*)d_in[4];
    const float* b_lin  = (const float*)d_in[5];
    const float* W_gate = (const float*)d_in[6];
    const float* b_gate = (const float*)d_in[7];
    const float* gamma  = (const float*)d_in[8];
    const float* beta   = (const float*)d_in[9];
    float* out = (float*)d_out;

    k_init<<<(N_NODES + 255) / 256, 256>>>();
    k_degree<<<(N_EDGES + 255) / 256, 256>>>(ei);
    k_scan<<<1, 1024>>>();
    k_fill<<<(N_EDGES + 255) / 256, 256>>>(ei);
    k_gcn_gemm<<<N_NODES / NB, D_HID>>>(xs, W_gcn);
    k_gather<<<N_NODES / 4, 256>>>(b_gcn);
    k_gate<<<N_NODES / NB, D_HID>>>(xs, W_gate, b_gate, W_lin, b_lin, out);
    k_bn<<<(N_NODES * D_HID + 255) / 256, 256>>>(out, gamma, beta);
}

// round 11
// speedup vs baseline: 1.3983x; 1.1220x over previous
#include <cuda_runtime.h>
#include <math.h>

#define N_NODES 50000
#define N_EDGES 800000
#define D_IN    64
#define D_HID   256
#define BN_EPS  1e-5f
#define NB      8   // nodes per block in GEMM kernels

// ---------------- scratch (no allocs allowed) ----------------
__device__ float g_dinv[N_NODES];
__device__ __align__(16) float g_xp[(size_t)N_NODES * D_IN];   // xs * dinv[row]
__device__ __align__(16) float g_y[(size_t)N_NODES * D_IN];    // aggregated inputs
__device__ __align__(16) float g_z[(size_t)N_NODES * D_HID];   // tanh(y @ W_gcn + b)
__device__ float g_sum[D_HID];
__device__ float g_sumsq[D_HID];
// CSR scratch
__device__ int g_deg[N_NODES];
__device__ int g_rowptr[N_NODES + 1];
__device__ int g_cursor[N_NODES];
__device__ int g_csrc[N_EDGES];

// ---------------- packed f32x2 helpers (FFMA2 on sm_103a) ----------------
__device__ __forceinline__ unsigned long long pk2(float lo, float hi) {
    unsigned long long r;
    asm("mov.b64 %0, {%1, %2};" : "=l"(r) : "f"(lo), "f"(hi));
    return r;
}
__device__ __forceinline__ float2 upk2(unsigned long long v) {
    float2 f;
    asm("mov.b64 {%0, %1}, %2;" : "=f"(f.x), "=f"(f.y) : "l"(v));
    return f;
}
__device__ __forceinline__ void fma2(unsigned long long& d, unsigned long long a,
                                     unsigned long long b) {
    asm("fma.rn.f32x2 %0, %1, %2, %0;" : "+l"(d) : "l"(a), "l"(b));
}

// ---------------- K0: zero degree + BN stats ----------------
__global__ void k_init() {
    int i = blockIdx.x * blockDim.x + threadIdx.x;
    if (i < N_NODES) g_deg[i] = 0;
    if (i < D_HID) { g_sum[i] = 0.0f; g_sumsq[i] = 0.0f; }
}

// ---------------- K1: degree histogram over dst ----------------
__global__ void k_degree(const int* __restrict__ ei) {
    int e = blockIdx.x * blockDim.x + threadIdx.x;
    if (e < N_EDGES) atomicAdd(&g_deg[ei[N_EDGES + e]], 1);
}

// ---------------- K2: single-block prefix scan -> rowptr/cursor, dinv ----------------
__global__ void __launch_bounds__(1024) k_scan() {
    __shared__ int warpsums[32];
    int t = threadIdx.x, lane = t & 31, w = t >> 5;
    int carry = 0;
    for (int base = 0; base < N_NODES; base += 1024) {
        int i = base + t;
        int v = (i < N_NODES) ? g_deg[i] : 0;
        int x = v;
#pragma unroll
        for (int off = 1; off < 32; off <<= 1) {
            int y = __shfl_up_sync(0xffffffffu, x, off);
            if (lane >= off) x += y;
        }
        if (lane == 31) warpsums[w] = x;
        __syncthreads();
        if (w == 0) {
            int s = warpsums[lane];
#pragma unroll
            for (int off = 1; off < 32; off <<= 1) {
                int y = __shfl_up_sync(0xffffffffu, s, off);
                if (lane >= off) s += y;
            }
            warpsums[lane] = s;
        }
        __syncthreads();
        int woff = (w > 0) ? warpsums[w - 1] : 0;
        int excl = carry + woff + x - v;
        if (i < N_NODES) {
            g_rowptr[i] = excl;
            g_cursor[i] = excl;
            g_dinv[i] = rsqrtf((float)(v + 1));   // +1 self loop
        }
        int tile_total = warpsums[31];
        __syncthreads();   // protect warpsums before next tile overwrites
        carry += tile_total;
    }
    if (t == 0) g_rowptr[N_NODES] = carry;
}

// ---------------- K3: CSR fill ----------------
__global__ void k_fill(const int* __restrict__ ei) {
    int e = blockIdx.x * blockDim.x + threadIdx.x;
    if (e < N_EDGES) {
        int s = ei[e];
        int d = ei[N_EDGES + e];
        int pos = atomicAdd(&g_cursor[d], 1);
        g_csrc[pos] = s;
    }
}

// ---------------- K3b: xs' = xs * dinv[row] ----------------
__global__ void k_xscale(const float* __restrict__ xs) {
    int i = blockIdx.x * blockDim.x + threadIdx.x;   // float4 index, 800000 total
    if (i < N_NODES * D_IN / 4) {
        float di = g_dinv[i >> 4];                   // 16 float4 per row
        float4 v = ((const float4*)xs)[i];
        v.x *= di; v.y *= di; v.z *= di; v.w *= di;
        ((float4*)g_xp)[i] = v;
    }
}

// ---------------- K4: CSR gather in D_IN space: y = dinv[dst]*(xs'[dst] + sum xs'[src]) ----------------
__global__ void __launch_bounds__(256) k_gather_x() {
    int t = threadIdx.x;
    int n = blockIdx.x * 16 + (t >> 4);   // 16 nodes/block, 16 threads each
    int c = t & 15;                       // float4 column (64 floats = 16 float4)
    int g0 = t & ~15;                     // first lane of this node's 16-thread group
    const float4* X = (const float4*)g_xp;

    // one thread per group loads node scalars; broadcast via shuffle
    int r_s = 0, e_s = 0;
    float di_s = 0.0f;
    if (c == 0) {
        r_s = g_rowptr[n];
        e_s = g_rowptr[n + 1];
        di_s = g_dinv[n];
    }
    int r  = __shfl_sync(0xffffffffu, r_s, g0 & 31);
    int e  = __shfl_sync(0xffffffffu, e_s, g0 & 31);
    float di = __shfl_sync(0xffffffffu, di_s, g0 & 31);

    float4 acc = X[(size_t)n * 16 + c];   // self-loop term
    for (; r + 4 <= e; r += 4) {
        int i0 = __ldg(&g_csrc[r]);
        int i1 = __ldg(&g_csrc[r + 1]);
        int i2 = __ldg(&g_csrc[r + 2]);
        int i3 = __ldg(&g_csrc[r + 3]);
        float4 a0 = X[(size_t)i0 * 16 + c];
        float4 a1 = X[(size_t)i1 * 16 + c];
        float4 a2 = X[(size_t)i2 * 16 + c];
        float4 a3 = X[(size_t)i3 * 16 + c];
        acc.x += (a0.x + a1.x) + (a2.x + a3.x);
        acc.y += (a0.y + a1.y) + (a2.y + a3.y);
        acc.z += (a0.z + a1.z) + (a2.z + a3.z);
        acc.w += (a0.w + a1.w) + (a2.w + a3.w);
    }
    for (; r < e; r++) {
        float4 a0 = X[(size_t)__ldg(&g_csrc[r]) * 16 + c];
        acc.x += a0.x; acc.y += a0.y; acc.z += a0.z; acc.w += a0.w;
    }
    acc.x *= di; acc.y *= di; acc.z *= di; acc.w *= di;
    ((float4*)g_y)[(size_t)n * 16 + c] = acc;
}

// ---------------- K5: z = tanh(y @ W_gcn + b_gcn)  (FFMA2) ----------------
__global__ void __launch_bounds__(D_HID) k_gcn_gemm(const float* __restrict__ Wg,
                                                    const float* __restrict__ b_gcn) {
    __shared__ __align__(16) float sy[NB * D_IN];
    int n0 = blockIdx.x * NB;
    int j  = threadIdx.x;

    sy[j]       = g_y[(size_t)n0 * D_IN + j];
    sy[j + 256] = g_y[(size_t)n0 * D_IN + 256 + j];
    __syncthreads();

    unsigned long long acc2[NB];
#pragma unroll
    for (int nb = 0; nb < NB; nb++) acc2[nb] = 0ULL;

#pragma unroll 4
    for (int k4 = 0; k4 < D_IN / 4; k4++) {
        float w0 = Wg[(4 * k4 + 0) * D_HID + j];
        float w1 = Wg[(4 * k4 + 1) * D_HID + j];
        float w2 = Wg[(4 * k4 + 2) * D_HID + j];
        float w3 = Wg[(4 * k4 + 3) * D_HID + j];
        unsigned long long wp0 = pk2(w0, w1), wp1 = pk2(w2, w3);
#pragma unroll
        for (int nb = 0; nb < NB; nb++) {
            ulonglong2 yy = ((const ulonglong2*)(sy + nb * D_IN))[k4];
            fma2(acc2[nb], yy.x, wp0);
            fma2(acc2[nb], yy.y, wp1);
        }
    }

    float b = b_gcn[j];
#pragma unroll
    for (int nb = 0; nb < NB; nb++) {
        float2 f = upk2(acc2[nb]);
        g_z[(size_t)(n0 + nb) * D_HID + j] = tanhf(f.x + f.y + b);
    }
}

// ---------------- K6: gate GEMM + lin GEMM + residual + relu + BN stats (FFMA2) ----------------
__global__ void __launch_bounds__(D_HID) k_gate(const float* __restrict__ xs,
                                                const float* __restrict__ Wgate,
                                                const float* __restrict__ b_gate,
                                                const float* __restrict__ Wlin,
                                                const float* __restrict__ b_lin,
                                                float* __restrict__ out) {
    __shared__ __align__(16) float sz[NB * D_HID];   // 8 z rows (8 KB)
    __shared__ __align__(16) float sx[NB * D_IN];    // 8 xs rows (2 KB)
    int n0 = blockIdx.x * NB;
    int j  = threadIdx.x;

#pragma unroll
    for (int t = 0; t < NB; t++)
        sz[j + 256 * t] = g_z[(size_t)n0 * D_HID + j + 256 * t];
    sx[j]       = xs[(size_t)n0 * D_IN + j];
    sx[j + 256] = xs[(size_t)n0 * D_IN + 256 + j];
    __syncthreads();

    unsigned long long accg2[NB], accl2[NB];
#pragma unroll
    for (int nb = 0; nb < NB; nb++) { accg2[nb] = 0ULL; accl2[nb] = 0ULL; }

    // gate GEMM: K = 256, packed over k
#pragma unroll 4
    for (int k4 = 0; k4 < D_HID / 4; k4++) {
        float w0 = Wgate[(4 * k4 + 0) * D_HID + j];
        float w1 = Wgate[(4 * k4 + 1) * D_HID + j];
        float w2 = Wgate[(4 * k4 + 2) * D_HID + j];
        float w3 = Wgate[(4 * k4 + 3) * D_HID + j];
        unsigned long long wp0 = pk2(w0, w1), wp1 = pk2(w2, w3);
#pragma unroll
        for (int nb = 0; nb < NB; nb++) {
            ulonglong2 zz = ((const ulonglong2*)(sz + nb * D_HID))[k4];
            fma2(accg2[nb], zz.x, wp0);
            fma2(accg2[nb], zz.y, wp1);
        }
    }

    // lin GEMM: K = 64, packed over k
#pragma unroll 4
    for (int k4 = 0; k4 < D_IN / 4; k4++) {
        float w0 = Wlin[(4 * k4 + 0) * D_HID + j];
        float w1 = Wlin[(4 * k4 + 1) * D_HID + j];
        float w2 = Wlin[(4 * k4 + 2) * D_HID + j];
        float w3 = Wlin[(4 * k4 + 3) * D_HID + j];
        unsigned long long wp0 = pk2(w0, w1), wp1 = pk2(w2, w3);
#pragma unroll
        for (int nb = 0; nb < NB; nb++) {
            ulonglong2 xx = ((const ulonglong2*)(sx + nb * D_IN))[k4];
            fma2(accl2[nb], xx.x, wp0);
            fma2(accl2[nb], xx.y, wp1);
        }
    }

    float bg = b_gate[j], bl = b_lin[j];
    float s_loc = 0.0f, q_loc = 0.0f;
#pragma unroll
    for (int nb = 0; nb < NB; nb++) {
        float2 fg = upk2(accg2[nb]);
        float2 fl = upk2(accl2[nb]);
        float ag = fg.x + fg.y + bg;
        float al = fl.x + fl.y + bl;
        float g  = 1.0f / (1.0f + expf(-ag));
        float z  = sz[nb * D_HID + j];
        float o  = fmaxf((1.0f - g) * al + g * z, 0.0f);
        out[(size_t)(n0 + nb) * D_HID + j] = o;
        s_loc += o;
        q_loc += o * o;
    }
    atomicAdd(&g_sum[j], s_loc);
    atomicAdd(&g_sumsq[j], q_loc);
}

// ---------------- K7: BN normalize in place (float4) ----------------
__global__ void k_bn(float* __restrict__ out,
                     const float* __restrict__ gamma,
                     const float* __restrict__ beta) {
    int i = blockIdx.x * blockDim.x + threadIdx.x;   // float4 index
    if (i < N_NODES * D_HID / 4) {
        int c4 = i & 63;                             // 64 float4 per row
        const float invN = 1.0f / (float)N_NODES;
        float4 s  = ((const float4*)g_sum)[c4];
        float4 q  = ((const float4*)g_sumsq)[c4];
        float4 gm = ((const float4*)gamma)[c4];
        float4 bt = ((const float4*)beta)[c4];
        float4 v  = ((float4*)out)[i];
        float mu, var;
        mu = s.x * invN; var = q.x * invN - mu * mu;
        v.x = (v.x - mu) * rsqrtf(var + BN_EPS) * gm.x + bt.x;
        mu = s.y * invN; var = q.y * invN - mu * mu;
        v.y = (v.y - mu) * rsqrtf(var + BN_EPS) * gm.y + bt.y;
        mu = s.z * invN; var = q.z * invN - mu * mu;
        v.z = (v.z - mu) * rsqrtf(var + BN_EPS) * gm.z + bt.z;
        mu = s.w * invN; var = q.w * invN - mu * mu;
        v.w = (v.w - mu) * rsqrtf(var + BN_EPS) * gm.w + bt.w;
        ((float4*)out)[i] = v;
    }
}

// ---------------- launch ----------------
extern "C" void kernel_launch(void* const* d_in, const int* in_sizes, int n_in,
                              void* d_out, int out_size) {
    const float* xs     = (const float*)d_in[0];
    const int*   ei     = (const int*)d_in[1];   // int32 (JAX x64-disabled)
    const float* W_gcn  = (const float*)d_in[2];
    const float* b_gcn  = (const float*)d_in[3];
    const float* W_lin  = (const float*)d_in[4];
    const float* b_lin  = (const float*)d_in[5];
    const float* W_gate = (const float*)d_in[6];
    const float* b_gate = (const float*)d_in[7];
    const float* gamma  = (const float*)d_in[8];
    const float* beta   = (const float*)d_in[9];
    float* out = (float*)d_out;

    k_init<<<(N_NODES + 255) / 256, 256>>>();
    k_degree<<<(N_EDGES + 255) / 256, 256>>>(ei);
    k_scan<<<1, 1024>>>();
    k_fill<<<(N_EDGES + 255) / 256, 256>>>(ei);
    k_xscale<<<(N_NODES * D_IN / 4 + 255) / 256, 256>>>(xs);
    k_gather_x<<<N_NODES / 16, 256>>>();
    k_gcn_gemm<<<N_NODES / NB, D_HID>>>(W_gcn, b_gcn);
    k_gate<<<N_NODES / NB, D_HID>>>(xs, W_gate, b_gate, W_lin, b_lin, out);
    k_bn<<<(N_NODES * D_HID / 4 + 255) / 256, 256>>>(out, gamma, beta);
}

// round 12
// speedup vs baseline: 1.6024x; 1.1459x over previous
#include <cuda_runtime.h>
#include <math.h>

#define N_NODES 50000
#define N_EDGES 800000
#define D_IN    64
#define D_HID   256
#define BN_EPS  1e-5f
#define NB      16   // nodes per block in GEMM kernels
#define N_CHUNKS ((N_NODES + 1023) / 1024)   // 49

// ---------------- scratch (no allocs allowed) ----------------
__device__ float g_dinv[N_NODES];
__device__ __align__(16) float g_xp[(size_t)N_NODES * D_IN];   // xs * dinv[row]
__device__ __align__(16) float g_y[(size_t)N_NODES * D_IN];    // aggregated inputs
__device__ __align__(16) float g_z[(size_t)N_NODES * D_HID];   // tanh(y @ W_gcn + b)
__device__ float g_sum[D_HID];
__device__ float g_sumsq[D_HID];
// CSR scratch
__device__ int g_deg[N_NODES];
__device__ int g_rowptr[N_NODES + 1];
__device__ int g_cursor[N_NODES];
__device__ int g_csrc[N_EDGES];
__device__ int g_btot[N_CHUNKS];
__device__ int g_boff[N_CHUNKS];

// ---------------- packed f32x2 helpers (FFMA2 on sm_103a) ----------------
__device__ __forceinline__ unsigned long long pk2(float lo, float hi) {
    unsigned long long r;
    asm("mov.b64 %0, {%1, %2};" : "=l"(r) : "f"(lo), "f"(hi));
    return r;
}
__device__ __forceinline__ float2 upk2(unsigned long long v) {
    float2 f;
    asm("mov.b64 {%0, %1}, %2;" : "=f"(f.x), "=f"(f.y) : "l"(v));
    return f;
}
__device__ __forceinline__ void fma2(unsigned long long& d, unsigned long long a,
                                     unsigned long long b) {
    asm("fma.rn.f32x2 %0, %1, %2, %0;" : "+l"(d) : "l"(a), "l"(b));
}

// ---------------- K0: zero degree + BN stats ----------------
__global__ void k_init() {
    int i = blockIdx.x * blockDim.x + threadIdx.x;
    if (i < N_NODES) g_deg[i] = 0;
    if (i < D_HID) { g_sum[i] = 0.0f; g_sumsq[i] = 0.0f; }
}

// ---------------- K1: degree histogram over dst ----------------
__global__ void k_degree(const int* __restrict__ ei) {
    int e = blockIdx.x * blockDim.x + threadIdx.x;
    if (e < N_EDGES) atomicAdd(&g_deg[ei[N_EDGES + e]], 1);
}

// ---------------- K2a: per-1024-chunk exclusive scan + chunk totals ----------------
__global__ void __launch_bounds__(1024) k_scan1() {
    __shared__ int warpsums[32];
    int t = threadIdx.x, lane = t & 31, w = t >> 5;
    int i = blockIdx.x * 1024 + t;
    int v = (i < N_NODES) ? g_deg[i] : 0;
    int x = v;
#pragma unroll
    for (int off = 1; off < 32; off <<= 1) {
        int y = __shfl_up_sync(0xffffffffu, x, off);
        if (lane >= off) x += y;
    }
    if (lane == 31) warpsums[w] = x;
    __syncthreads();
    if (w == 0) {
        int s = warpsums[lane];
#pragma unroll
        for (int off = 1; off < 32; off <<= 1) {
            int y = __shfl_up_sync(0xffffffffu, s, off);
            if (lane >= off) s += y;
        }
        warpsums[lane] = s;
    }
    __syncthreads();
    int excl = ((w > 0) ? warpsums[w - 1] : 0) + x - v;
    if (i < N_NODES) g_rowptr[i] = excl;
    if (t == 0) g_btot[blockIdx.x] = warpsums[31];
}

// ---------------- K2b: scan 49 chunk totals (1 block, 64 threads) ----------------
__global__ void k_scan2() {
    __shared__ int w0tot;
    int t = threadIdx.x, lane = t & 31, w = t >> 5;
    int v = (t < N_CHUNKS) ? g_btot[t] : 0;
    int x = v;
#pragma unroll
    for (int off = 1; off < 32; off <<= 1) {
        int y = __shfl_up_sync(0xffffffffu, x, off);
        if (lane >= off) x += y;
    }
    if (w == 0 && lane == 31) w0tot = x;
    __syncthreads();
    int excl = x - v + (w ? w0tot : 0);
    if (t < N_CHUNKS) g_boff[t] = excl;
    if (t == N_CHUNKS - 1) g_rowptr[N_NODES] = excl + v;
}

// ---------------- K2c: apply chunk offsets; cursor; dinv ----------------
__global__ void k_scan3() {
    int i = blockIdx.x * blockDim.x + threadIdx.x;
    if (i < N_NODES) {
        int rp = g_rowptr[i] + g_boff[i >> 10];
        g_rowptr[i] = rp;
        g_cursor[i] = rp;
        g_dinv[i] = rsqrtf((float)(g_deg[i] + 1));   // +1 self loop
    }
}

// ---------------- K3: CSR fill ----------------
__global__ void k_fill(const int* __restrict__ ei) {
    int e = blockIdx.x * blockDim.x + threadIdx.x;
    if (e < N_EDGES) {
        int s = ei[e];
        int d = ei[N_EDGES + e];
        int pos = atomicAdd(&g_cursor[d], 1);
        g_csrc[pos] = s;
    }
}

// ---------------- K3b: xs' = xs * dinv[row] ----------------
__global__ void k_xscale(const float* __restrict__ xs) {
    int i = blockIdx.x * blockDim.x + threadIdx.x;   // float4 index
    if (i < N_NODES * D_IN / 4) {
        float di = g_dinv[i >> 4];                   // 16 float4 per row
        float4 v = ((const float4*)xs)[i];
        v.x *= di; v.y *= di; v.z *= di; v.w *= di;
        ((float4*)g_xp)[i] = v;
    }
}

// ---------------- K4: CSR gather in D_IN space ----------------
__global__ void __launch_bounds__(256) k_gather_x() {
    int t = threadIdx.x;
    int n = blockIdx.x * 16 + (t >> 4);   // 16 nodes/block, 16 threads each
    int c = t & 15;                       // float4 column
    int g0 = t & ~15;
    const float4* X = (const float4*)g_xp;

    int r_s = 0, e_s = 0;
    float di_s = 0.0f;
    if (c == 0) {
        r_s = g_rowptr[n];
        e_s = g_rowptr[n + 1];
        di_s = g_dinv[n];
    }
    int r  = __shfl_sync(0xffffffffu, r_s, g0 & 31);
    int e  = __shfl_sync(0xffffffffu, e_s, g0 & 31);
    float di = __shfl_sync(0xffffffffu, di_s, g0 & 31);

    float4 acc = X[(size_t)n * 16 + c];   // self-loop term
    for (; r + 4 <= e; r += 4) {
        int i0 = __ldg(&g_csrc[r]);
        int i1 = __ldg(&g_csrc[r + 1]);
        int i2 = __ldg(&g_csrc[r + 2]);
        int i3 = __ldg(&g_csrc[r + 3]);
        float4 a0 = X[(size_t)i0 * 16 + c];
        float4 a1 = X[(size_t)i1 * 16 + c];
        float4 a2 = X[(size_t)i2 * 16 + c];
        float4 a3 = X[(size_t)i3 * 16 + c];
        acc.x += (a0.x + a1.x) + (a2.x + a3.x);
        acc.y += (a0.y + a1.y) + (a2.y + a3.y);
        acc.z += (a0.z + a1.z) + (a2.z + a3.z);
        acc.w += (a0.w + a1.w) + (a2.w + a3.w);
    }
    for (; r < e; r++) {
        float4 a0 = X[(size_t)__ldg(&g_csrc[r]) * 16 + c];
        acc.x += a0.x; acc.y += a0.y; acc.z += a0.z; acc.w += a0.w;
    }
    acc.x *= di; acc.y *= di; acc.z *= di; acc.w *= di;
    ((float4*)g_y)[(size_t)n * 16 + c] = acc;
}

// ---------------- K5: z = tanh(y @ W_gcn + b_gcn)  (FFMA2, NB=16) ----------------
__global__ void __launch_bounds__(D_HID, 2) k_gcn_gemm(const float* __restrict__ Wg,
                                                       const float* __restrict__ b_gcn) {
    __shared__ __align__(16) float sy[NB * D_IN];   // 4 KB
    int n0 = blockIdx.x * NB;
    int j  = threadIdx.x;

#pragma unroll
    for (int t = 0; t < NB * D_IN / D_HID; t++)
        sy[j + 256 * t] = g_y[(size_t)n0 * D_IN + j + 256 * t];
    __syncthreads();

    unsigned long long acc2[NB];
#pragma unroll
    for (int nb = 0; nb < NB; nb++) acc2[nb] = 0ULL;

#pragma unroll 4
    for (int k4 = 0; k4 < D_IN / 4; k4++) {
        float w0 = Wg[(4 * k4 + 0) * D_HID + j];
        float w1 = Wg[(4 * k4 + 1) * D_HID + j];
        float w2 = Wg[(4 * k4 + 2) * D_HID + j];
        float w3 = Wg[(4 * k4 + 3) * D_HID + j];
        unsigned long long wp0 = pk2(w0, w1), wp1 = pk2(w2, w3);
#pragma unroll
        for (int nb = 0; nb < NB; nb++) {
            ulonglong2 yy = ((const ulonglong2*)(sy + nb * D_IN))[k4];
            fma2(acc2[nb], yy.x, wp0);
            fma2(acc2[nb], yy.y, wp1);
        }
    }

    float b = b_gcn[j];
#pragma unroll
    for (int nb = 0; nb < NB; nb++) {
        float2 f = upk2(acc2[nb]);
        g_z[(size_t)(n0 + nb) * D_HID + j] = tanhf(f.x + f.y + b);
    }
}

// ---------------- K6: gate GEMM + lin GEMM + residual + relu + BN stats (FFMA2, NB=16) ----------------
__global__ void __launch_bounds__(D_HID, 2) k_gate(const float* __restrict__ xs,
                                                   const float* __restrict__ Wgate,
                                                   const float* __restrict__ b_gate,
                                                   const float* __restrict__ Wlin,
                                                   const float* __restrict__ b_lin,
                                                   float* __restrict__ out) {
    __shared__ __align__(16) float sz[NB * D_HID];   // 16 KB
    __shared__ __align__(16) float sx[NB * D_IN];    // 4 KB
    int n0 = blockIdx.x * NB;
    int j  = threadIdx.x;

#pragma unroll
    for (int t = 0; t < NB; t++)
        sz[j + 256 * t] = g_z[(size_t)n0 * D_HID + j + 256 * t];
#pragma unroll
    for (int t = 0; t < NB * D_IN / D_HID; t++)
        sx[j + 256 * t] = xs[(size_t)n0 * D_IN + j + 256 * t];
    __syncthreads();

    unsigned long long accg2[NB];
#pragma unroll
    for (int nb = 0; nb < NB; nb++) accg2[nb] = 0ULL;

    // gate GEMM: K = 256, packed over k
#pragma unroll 2
    for (int k4 = 0; k4 < D_HID / 4; k4++) {
        float w0 = Wgate[(4 * k4 + 0) * D_HID + j];
        float w1 = Wgate[(4 * k4 + 1) * D_HID + j];
        float w2 = Wgate[(4 * k4 + 2) * D_HID + j];
        float w3 = Wgate[(4 * k4 + 3) * D_HID + j];
        unsigned long long wp0 = pk2(w0, w1), wp1 = pk2(w2, w3);
#pragma unroll
        for (int nb = 0; nb < NB; nb++) {
            ulonglong2 zz = ((const ulonglong2*)(sz + nb * D_HID))[k4];
            fma2(accg2[nb], zz.x, wp0);
            fma2(accg2[nb], zz.y, wp1);
        }
    }
    // collapse gate acc to scalar before lin loop (frees registers)
    float ag[NB];
#pragma unroll
    for (int nb = 0; nb < NB; nb++) {
        float2 fg = upk2(accg2[nb]);
        ag[nb] = fg.x + fg.y;
    }

    unsigned long long accl2[NB];
#pragma unroll
    for (int nb = 0; nb < NB; nb++) accl2[nb] = 0ULL;

    // lin GEMM: K = 64, packed over k
#pragma unroll 4
    for (int k4 = 0; k4 < D_IN / 4; k4++) {
        float w0 = Wlin[(4 * k4 + 0) * D_HID + j];
        float w1 = Wlin[(4 * k4 + 1) * D_HID + j];
        float w2 = Wlin[(4 * k4 + 2) * D_HID + j];
        float w3 = Wlin[(4 * k4 + 3) * D_HID + j];
        unsigned long long wp0 = pk2(w0, w1), wp1 = pk2(w2, w3);
#pragma unroll
        for (int nb = 0; nb < NB; nb++) {
            ulonglong2 xx = ((const ulonglong2*)(sx + nb * D_IN))[k4];
            fma2(accl2[nb], xx.x, wp0);
            fma2(accl2[nb], xx.y, wp1);
        }
    }

    float bg = b_gate[j], bl = b_lin[j];
    float s_loc = 0.0f, q_loc = 0.0f;
#pragma unroll
    for (int nb = 0; nb < NB; nb++) {
        float2 fl = upk2(accl2[nb]);
        float al = fl.x + fl.y + bl;
        float g  = 1.0f / (1.0f + expf(-(ag[nb] + bg)));
        float z  = sz[nb * D_HID + j];
        float o  = fmaxf((1.0f - g) * al + g * z, 0.0f);
        out[(size_t)(n0 + nb) * D_HID + j] = o;
        s_loc += o;
        q_loc += o * o;
    }
    atomicAdd(&g_sum[j], s_loc);
    atomicAdd(&g_sumsq[j], q_loc);
}

// ---------------- K7: BN normalize in place (float4) ----------------
__global__ void k_bn(float* __restrict__ out,
                     const float* __restrict__ gamma,
                     const float* __restrict__ beta) {
    int i = blockIdx.x * blockDim.x + threadIdx.x;   // float4 index
    if (i < N_NODES * D_HID / 4) {
        int c4 = i & 63;
        const float invN = 1.0f / (float)N_NODES;
        float4 s  = ((const float4*)g_sum)[c4];
        float4 q  = ((const float4*)g_sumsq)[c4];
        float4 gm = ((const float4*)gamma)[c4];
        float4 bt = ((const float4*)beta)[c4];
        float4 v  = ((float4*)out)[i];
        float mu, var;
        mu = s.x * invN; var = q.x * invN - mu * mu;
        v.x = (v.x - mu) * rsqrtf(var + BN_EPS) * gm.x + bt.x;
        mu = s.y * invN; var = q.y * invN - mu * mu;
        v.y = (v.y - mu) * rsqrtf(var + BN_EPS) * gm.y + bt.y;
        mu = s.z * invN; var = q.z * invN - mu * mu;
        v.z = (v.z - mu) * rsqrtf(var + BN_EPS) * gm.z + bt.z;
        mu = s.w * invN; var = q.w * invN - mu * mu;
        v.w = (v.w - mu) * rsqrtf(var + BN_EPS) * gm.w + bt.w;
        ((float4*)out)[i] = v;
    }
}

// ---------------- launch ----------------
extern "C" void kernel_launch(void* const* d_in, const int* in_sizes, int n_in,
                              void* d_out, int out_size) {
    const float* xs     = (const float*)d_in[0];
    const int*   ei     = (const int*)d_in[1];   // int32 (JAX x64-disabled)
    const float* W_gcn  = (const float*)d_in[2];
    const float* b_gcn  = (const float*)d_in[3];
    const float* W_lin  = (const float*)d_in[4];
    const float* b_lin  = (const float*)d_in[5];
    const float* W_gate = (const float*)d_in[6];
    const float* b_gate = (const float*)d_in[7];
    const float* gamma  = (const float*)d_in[8];
    const float* beta   = (const float*)d_in[9];
    float* out = (float*)d_out;

    k_init<<<(N_NODES + 255) / 256, 256>>>();
    k_degree<<<(N_EDGES + 255) / 256, 256>>>(ei);
    k_scan1<<<N_CHUNKS, 1024>>>();
    k_scan2<<<1, 64>>>();
    k_scan3<<<(N_NODES + 255) / 256, 256>>>();
    k_fill<<<(N_EDGES + 255) / 256, 256>>>(ei);
    k_xscale<<<(N_NODES * D_IN / 4 + 255) / 256, 256>>>(xs);
    k_gather_x<<<N_NODES / 16, 256>>>();
    k_gcn_gemm<<<N_NODES / NB, D_HID>>>(W_gcn, b_gcn);
    k_gate<<<N_NODES / NB, D_HID>>>(xs, W_gate, b_gate, W_lin, b_lin, out);
    k_bn<<<(N_NODES * D_HID / 4 + 255) / 256, 256>>>(out, gamma, beta);
}